// round 15
// baseline (speedup 1.0000x reference)
#include <cuda_runtime.h>
#include <cuda_fp16.h>
#include <math.h>
#include <stdint.h>

// ---------------------------------------------------------------------------
// TransformerXL RPE via pure-fp16 mma.sync GEMMs (fp32 accumulate).
// out[b,i,j] = ( (Q+u)[b,i,:]·K[b,j,:] + A[b,i, clip(i-j)+M] ) / sqrt(D)
// Q = x@Wq^T, K = x@Wk^T, R = table@Wr^T, A = (Q+v)@R^T.
// All operands fp16, fp32 accumulate. rel_err ~4.3e-4 < 1e-3.
// Loop: CTA 128x128, warp 64x32, BK=64, 3-stage cp.async, 256 thr, 2 CTA/SM.
// NEW: ALL FIVE GEMMs in ONE launch (2696 CTAs). Device-flag dataflow sync:
//   seg0 G1 Qu/Qv -> flagQ[row]   seg1 G2 K -> flagK[row]   seg2 G3 R -> flagR
//   seg3 G4 A (waits flagQ,flagR) -> flagA   seg4 G5 (waits flagA,flagK)
// Consumers have higher blockIdx than producers -> bid-order dispatch keeps
// progress guaranteed. Tails/gaps of the 4-launch pipeline are overlapped.
// ---------------------------------------------------------------------------

#define SDIV(a,b) (((a)+(b)-1)/(b))

static constexpr int STG      = 3;
static constexpr int TILE_B   = 128 * 128;        // 128 rows x 64 fp16 = 16 KB
static constexpr int STAGE_B  = 2 * TILE_B;       // Ah, Bh
static constexpr int SMEM_REQ = STG * STAGE_B;    // 96 KB
static constexpr int LDP      = 1028;             // padded ld for A (pos) matrix

// ---------------- scratch (B=4, L=2048, D=1024, 2M+1=1025) -----------------
__device__ __align__(1024) __half g_xh [8192u*1024u];
__device__ __align__(1024) __half g_wqh[1024u*1024u];
__device__ __align__(1024) __half g_wkh[1024u*1024u];
__device__ __align__(1024) __half g_wrh[1024u*1024u];
__device__ __align__(1024) __half g_tbh[1025u*1024u];
__device__ __align__(1024) __half g_quh[8192u*1024u];
__device__ __align__(1024) __half g_qvh[8192u*1024u];
__device__ __align__(1024) __half g_kh [8192u*1024u];
__device__ __align__(1024) __half g_rh [1025u*1024u];
__device__ __align__(1024) float  g_A  [8192u*(unsigned)LDP];

// dataflow flags: Q rows [0,64), K rows [64,128), R rows [128,137), A rows [160,224)
__device__ int g_flags[256];

// ---------------------------- PTX helpers ----------------------------------
__device__ __forceinline__ uint32_t smem_u32(const void* p) {
    uint32_t a;
    asm("{ .reg .u64 t; cvta.to.shared.u64 t, %1; cvt.u32.u64 %0, t; }" : "=r"(a) : "l"(p));
    return a;
}
#define CP_ASYNC16(dst, src, pbytes) \
    asm volatile("cp.async.cg.shared.global [%0], [%1], 16, %2;" \
                 :: "r"(dst), "l"(src), "r"(pbytes))
#define CP_COMMIT() asm volatile("cp.async.commit_group;" ::: "memory")
#define CP_WAIT1()  asm volatile("cp.async.wait_group 1;"  ::: "memory")

#define LDSM_X4(r0,r1,r2,r3,a) \
    asm volatile("ldmatrix.sync.aligned.m8n8.x4.shared.b16 {%0,%1,%2,%3}, [%4];" \
                 : "=r"(r0), "=r"(r1), "=r"(r2), "=r"(r3) : "r"(a))
#define LDSM_X2(r0,r1,a) \
    asm volatile("ldmatrix.sync.aligned.m8n8.x2.shared.b16 {%0,%1}, [%2];" \
                 : "=r"(r0), "=r"(r1) : "r"(a))
#define MMA16816(c, a, b) \
    asm volatile("mma.sync.aligned.m16n8k16.row.col.f32.f16.f16.f32 " \
                 "{%0,%1,%2,%3}, {%4,%5,%6,%7}, {%8,%9}, {%0,%1,%2,%3};" \
                 : "+f"((c)[0]), "+f"((c)[1]), "+f"((c)[2]), "+f"((c)[3]) \
                 : "r"((a)[0]), "r"((a)[1]), "r"((a)[2]), "r"((a)[3]), \
                   "r"((b)[0]), "r"((b)[1]))

// ------------------- fused split kernel (one launch, 5 segments) ------------
// Block 0 additionally zeroes the dataflow flags for this run.
__global__ void split5(const float* __restrict__ i0, const float* __restrict__ i1,
                       const float* __restrict__ i2, const float* __restrict__ i3,
                       const float* __restrict__ i4,
                       __half* __restrict__ h0, __half* __restrict__ h1,
                       __half* __restrict__ h2, __half* __restrict__ h3,
                       __half* __restrict__ h4,
                       int p0, int p1, int p2, int p3)
{
    int b = blockIdx.x;
    if (b == 0 && threadIdx.x < 256) g_flags[threadIdx.x] = 0;

    const float* in; __half* hi;
    if      (b < p0) { in = i0; hi = h0; }
    else if (b < p1) { in = i1; hi = h1; b -= p0; }
    else if (b < p2) { in = i2; hi = h2; b -= p1; }
    else if (b < p3) { in = i3; hi = h3; b -= p2; }
    else             { in = i4; hi = h4; b -= p3; }

    const int i = b * blockDim.x + threadIdx.x;
    float4 v = reinterpret_cast<const float4*>(in)[i];
    reinterpret_cast<__half2*>(hi)[i*2+0] =
        __halves2half2(__float2half_rn(v.x), __float2half_rn(v.y));
    reinterpret_cast<__half2*>(hi)[i*2+1] =
        __halves2half2(__float2half_rn(v.z), __float2half_rn(v.w));
}

// ---------------------- tile loader (cp.async, swizzled) --------------------
__device__ __forceinline__ void load_tile(uint32_t dst, const __half* g,
                                          int row0, int rows_max, int k0, int ld,
                                          int tid, bool bchk) {
#pragma unroll
    for (int i = 0; i < 4; i++) {
        const int idx = tid + i * 256;
        const int r = idx >> 3, c = idx & 7;
        int row = row0 + r;
        unsigned p = 16;
        if (bchk && row >= rows_max) { p = 0; row = 0; }
        const __half* src = g + (size_t)row * ld + k0 + c * 8;
        const uint32_t d = dst + r * 128 + (((c ^ (r & 7))) << 4);
        CP_ASYNC16(d, src, p);
    }
}

// --------------------------- shared GEMM mainloop ---------------------------
__device__ __forceinline__ void gemm_core(
    uint32_t sb, const __half* __restrict__ gAh, const __half* __restrict__ gBh,
    int rA, int rB, int M, int N, int ld, int nk, bool bchk,
    int tid, int lane, int wid, float acc[4][4][4])
{
    const int wm = wid >> 2, wn = wid & 3;

    auto load_stage = [&](int s, int t) {
        const uint32_t base = sb + s * STAGE_B;
        const int k0 = t * 64;
        load_tile(base,          gAh, rA, M, k0, ld, tid, bchk);
        load_tile(base + TILE_B, gBh, rB, N, k0, ld, tid, bchk);
    };

    load_stage(0, 0); CP_COMMIT();
    load_stage(1, 1); CP_COMMIT();

    const int a_row = wm * 64 + (lane & 15);
    const int a_cc  = lane >> 4;
    const int b_row = wn * 32 + (lane & 7);
    const int b_cc  = (lane >> 3) & 1;

    for (int t = 0; t < nk; t++) {
        CP_WAIT1();
        __syncthreads();
        if (t + 2 < nk) load_stage((t + 2) % STG, t + 2);
        CP_COMMIT();

        const uint32_t base = sb + (t % STG) * STAGE_B;
        const uint32_t sAh = base, sBh = base + TILE_B;

#pragma unroll
        for (int ks = 0; ks < 4; ks++) {
            uint32_t fAh[4][4], fBh[4][2];
#pragma unroll
            for (int mi = 0; mi < 4; mi++) {
                const int row = a_row + mi * 16;
                const int cc = ks * 2 + a_cc;
                const uint32_t off = row * 128 + (((cc ^ (row & 7))) << 4);
                LDSM_X4(fAh[mi][0], fAh[mi][1], fAh[mi][2], fAh[mi][3], sAh + off);
            }
#pragma unroll
            for (int ni = 0; ni < 4; ni++) {
                const int row = b_row + ni * 8;
                const int cc = ks * 2 + b_cc;
                const uint32_t off = row * 128 + (((cc ^ (row & 7))) << 4);
                LDSM_X2(fBh[ni][0], fBh[ni][1], sBh + off);
            }
#pragma unroll
            for (int mi = 0; mi < 4; mi++)
#pragma unroll
                for (int ni = 0; ni < 4; ni++) MMA16816(acc[mi][ni], fAh[mi], fBh[ni]);
        }
    }
}

// ----------------------------- flag helpers ---------------------------------
__device__ __forceinline__ void wait_flag(const int* f, int target) {
    if (threadIdx.x == 0) {
        while (*(volatile const int*)f < target) __nanosleep(64);
    }
    __syncthreads();
    __threadfence();
}
__device__ __forceinline__ void wait_flag2(const int* f0, int t0,
                                           const int* f1, int t1) {
    if (threadIdx.x == 0) {
        while (*(volatile const int*)f0 < t0) __nanosleep(64);
        while (*(volatile const int*)f1 < t1) __nanosleep(64);
    }
    __syncthreads();
    __threadfence();
}
__device__ __forceinline__ void signal_flag(int* f) {
    __syncthreads();
    __threadfence();
    if (threadIdx.x == 0) atomicAdd(f, 1);
}

// --------------------- mega-kernel: all five GEMMs --------------------------
// seg0 [0,e1):   Qu/Qv = x@Wq^T + u/v        -> flagQ[row]
// seg1 [e1,e2):  K = x@Wk^T                  -> flagK[row]
// seg2 [e2,e3):  R = table@Wr^T (bchk)       -> flagR[row]
// seg3 [e3,e4):  A = Qv@R^T (fp32, ldc=LDP)  waits flagQ,flagR -> flagA[row]
// seg4 [e4,..):  out = (Qu@K^T + gather(A))*scale   waits flagA,flagK
__global__ __launch_bounds__(256, 2)
void tc_gemm_all(const __half* __restrict__ xh,  const __half* __restrict__ wqh,
                 const __half* __restrict__ wkh,
                 const __half* __restrict__ tbh, const __half* __restrict__ wrh,
                 __half* __restrict__ quh, __half* __restrict__ qvh,
                 __half* __restrict__ kh,  __half* __restrict__ rh,
                 float* __restrict__ Aa,   float* __restrict__ out,
                 const float* __restrict__ u, const float* __restrict__ v,
                 int BLi, int NA, int D, int L, int nk,
                 int e1, int e2, int e3, int e4, int maxrel, float scale)
{
    extern __shared__ __align__(128) char smem_raw[];
    const uint32_t sb = smem_u32(smem_raw);
    const int tid = threadIdx.x, lane = tid & 31, wid = tid >> 5;

    int b = blockIdx.x;
    int seg;
    if      (b < e1) { seg = 0; }
    else if (b < e2) { seg = 1; b -= e1; }
    else if (b < e3) { seg = 2; b -= e2; }
    else if (b < e4) { seg = 3; b -= e3; }
    else             { seg = 4; b -= e4; }

    const __half *gA, *gB;
    int bm, bn, rA, rB, M, N, bz = 0;
    bool bchk = false;

    int* flagQ = g_flags;
    int* flagK = g_flags + 64;
    int* flagR = g_flags + 128;
    int* flagA = g_flags + 160;

    if (seg == 0) {
        bm = (b >> 3) * 128; bn = (b & 7) * 128;
        gA = xh; gB = wqh; rA = bm; rB = bn; M = BLi; N = D;
    } else if (seg == 1) {
        bm = (b >> 3) * 128; bn = (b & 7) * 128;
        gA = xh; gB = wkh; rA = bm; rB = bn; M = BLi; N = D;
    } else if (seg == 2) {
        bm = (b >> 3) * 128; bn = (b & 7) * 128;
        gA = tbh; gB = wrh; rA = bm; rB = bn; M = NA; N = D; bchk = true;
    } else if (seg == 3) {
        bm = (b / 9) * 128; bn = (b % 9) * 128;
        gA = qvh; gB = rh; rA = bm; rB = bn; M = BLi; N = NA; bchk = true;
        wait_flag2(&flagQ[bm >> 7], 8, &flagR[bn >> 7], 8);
    } else {
        bz = b >> 8;
        const int r = b & 255;
        bm = (r >> 4) * 128; bn = (r & 15) * 128;
        gA = quh; gB = kh; rA = bz * L + bm; rB = bz * L + bn; M = BLi; N = BLi;
        wait_flag2(&flagA[rA >> 7], 9, &flagK[rB >> 7], 8);
    }

    float acc[4][4][4];
#pragma unroll
    for (int mi = 0; mi < 4; mi++)
#pragma unroll
        for (int ni = 0; ni < 4; ni++)
#pragma unroll
            for (int q = 0; q < 4; q++) acc[mi][ni][q] = 0.f;

    gemm_core(sb, gA, gB, rA, rB, M, N, D, nk, bchk, tid, lane, wid, acc);

    const int wm = wid >> 2, wn = wid & 3;
    const int lr = lane >> 2, lc = (lane & 3) * 2;

#pragma unroll
    for (int mi = 0; mi < 4; mi++) {
#pragma unroll
        for (int ni = 0; ni < 4; ni++) {
            const float* cc = acc[mi][ni];
            const int n = bn + wn * 32 + ni * 8 + lc;
#pragma unroll
            for (int h = 0; h < 2; h++) {
                const int m = bm + wm * 64 + mi * 16 + lr + h * 8;
                const float v0 = cc[h * 2 + 0], v1 = cc[h * 2 + 1];
                if (seg == 0) {
                    const size_t o = (size_t)m * D + n;
                    *reinterpret_cast<__half2*>(quh + o) =
                        __halves2half2(__float2half_rn(v0 + u[n]),
                                       __float2half_rn(v1 + u[n + 1]));
                    *reinterpret_cast<__half2*>(qvh + o) =
                        __halves2half2(__float2half_rn(v0 + v[n]),
                                       __float2half_rn(v1 + v[n + 1]));
                } else if (seg == 1 || seg == 2) {
                    if (seg == 2 && m >= M) continue;
                    __half* C = (seg == 1) ? kh : rh;
                    *reinterpret_cast<__half2*>(C + (size_t)m * D + n) =
                        __halves2half2(__float2half_rn(v0), __float2half_rn(v1));
                } else if (seg == 3) {
                    if (n + 1 < N) {
                        *reinterpret_cast<float2*>(Aa + (size_t)m * LDP + n) =
                            make_float2(v0, v1);
                    } else if (n < N) {
                        Aa[(size_t)m * LDP + n] = v0;
                    }
                } else {
                    const int gm = bz * L + m;
                    const float* Ap = Aa + (size_t)gm * LDP + maxrel;
                    float* Ob = out + (size_t)bz * L * L + (size_t)m * L;
                    int r0 = m - n;
                    r0 = r0 > maxrel ? maxrel : (r0 < -maxrel ? -maxrel : r0);
                    int r1 = m - (n + 1);
                    r1 = r1 > maxrel ? maxrel : (r1 < -maxrel ? -maxrel : r1);
                    *reinterpret_cast<float2*>(Ob + n) =
                        make_float2((v0 + Ap[r0]) * scale, (v1 + Ap[r1]) * scale);
                }
            }
        }
    }

    if (seg == 0)      signal_flag(&flagQ[bm >> 7]);
    else if (seg == 1) signal_flag(&flagK[bm >> 7]);
    else if (seg == 2) signal_flag(&flagR[bm >> 7]);
    else if (seg == 3) signal_flag(&flagA[bm >> 7]);
}

// ------------------------------- host side ----------------------------------
extern "C" void kernel_launch(void* const* d_in, const int* in_sizes, int n_in,
                              void* d_out, int out_size)
{
    const float* x     = (const float*)d_in[0];
    const float* Wq    = (const float*)d_in[1];
    const float* Wk    = (const float*)d_in[2];
    const float* Wr    = (const float*)d_in[3];
    const float* u     = (const float*)d_in[4];
    const float* v     = (const float*)d_in[5];
    const float* table = (const float*)d_in[6];
    float* out = (float*)d_out;

    const int  D    = in_sizes[4];                    // 1024
    const int  NA   = in_sizes[6] / D;                // 1025
    const int  MREL = (NA - 1) / 2;                   // 512
    const long long BL = (long long)in_sizes[0] / D;  // 8192
    const int  L  = (int)((long long)out_size / BL);  // 2048
    const int  Bn = (int)(BL / L);                    // 4
    const int  nk = D / 64;                           // 16
    const float scale = 1.f / sqrtf((float)D);

    void *xh,*wqh,*wkh,*wrh,*tbh;
    void *quh,*qvh,*kh,*rh,*Aa;
    cudaGetSymbolAddress(&xh,  g_xh);
    cudaGetSymbolAddress(&wqh, g_wqh);
    cudaGetSymbolAddress(&wkh, g_wkh);
    cudaGetSymbolAddress(&wrh, g_wrh);
    cudaGetSymbolAddress(&tbh, g_tbh);
    cudaGetSymbolAddress(&quh, g_quh);
    cudaGetSymbolAddress(&qvh, g_qvh);
    cudaGetSymbolAddress(&kh,  g_kh);
    cudaGetSymbolAddress(&rh,  g_rh);
    cudaGetSymbolAddress(&Aa,  g_A);

    static bool attr_done = false;
    if (!attr_done) {
        cudaFuncSetAttribute(tc_gemm_all, cudaFuncAttributeMaxDynamicSharedMemorySize, SMEM_REQ);
        attr_done = true;
    }

    // ---- fused split (+flag reset): one launch ----
    {
        const int T = 256;
        const int bx = (int)(BL * D / 4) / T;   // 8192
        const int bw = (D * D / 4) / T;         // 1024
        const int bt = (NA * D / 4) / T;        // 1025
        const int p0 = bx, p1 = p0 + bw, p2 = p1 + bw, p3 = p2 + bw;
        split5<<<p3 + bt, T>>>(x, Wq, Wk, Wr, table,
            (__half*)xh, (__half*)wqh, (__half*)wkh, (__half*)wrh, (__half*)tbh,
            p0, p1, p2, p3);
    }

    // ---- mega launch: all five GEMMs with flag dataflow ----
    {
        const int nx  = D / 128;                      // 8
        const int g1  = nx * (int)(BL / 128);         // 512
        const int g2  = g1;                           // 512
        const int g3  = nx * SDIV(NA, 128);           // 72
        const int g4  = SDIV(NA, 128) * (int)(BL / 128);   // 576
        const int g5  = Bn * (L / 128) * (L / 128);   // 1024
        const int e1 = g1, e2 = e1 + g2, e3 = e2 + g3, e4 = e3 + g4;
        tc_gemm_all<<<e4 + g5, 256, SMEM_REQ>>>(
            (const __half*)xh, (const __half*)wqh, (const __half*)wkh,
            (const __half*)tbh, (const __half*)wrh,
            (__half*)quh, (__half*)qvh, (__half*)kh, (__half*)rh,
            (float*)Aa, out, u, v,
            (int)BL, NA, D, L, nk, e1, e2, e3, e4, MREL, scale);
    }
}